// round 1
// baseline (speedup 1.0000x reference)
#include <cuda_runtime.h>
#include <cuda_bf16.h>

// InverseAvgPool1d, K=8 -> half=4, s=9.
// out[t] = 8 * inclusive stride-9 scan of v[t], where
//   v[0]=0, v[t]=x[t]-x[t-1] (t>=1), v[5]+=x[0]   (per row of length 4096)

#define ROW_T 4096
#define NWARP 9
#define NTHREADS (NWARP * 32)
#define NTILES 15   // ceil(456/32)

__global__ __launch_bounds__(NTHREADS)
void inv_avgpool_kernel(const float* __restrict__ x, float* __restrict__ out) {
    __shared__ float s[ROW_T];

    const size_t row = blockIdx.x;
    const float4* __restrict__ xr = (const float4*)(x + row * ROW_T);
    float4* __restrict__ outr = (float4*)(out + row * ROW_T);

    // 1) coalesced stage: 1024 float4
    #pragma unroll
    for (int i = threadIdx.x; i < ROW_T / 4; i += NTHREADS) {
        ((float4*)s)[i] = xr[i];
    }
    __syncthreads();

    const int w = threadIdx.x >> 5;      // warp id = residue chain r
    const int lane = threadIdx.x & 31;
    const int r = w;
    const int n = (r == 0) ? 456 : 455;  // chain length

    // 2) gather v into registers (stride-9 LDS: conflict-free, gcd(9,32)=1)
    float v[NTILES];
    #pragma unroll
    for (int k = 0; k < NTILES; k++) {
        const int i = 32 * k + lane;
        float val = 0.f;
        if (i < n) {
            const int t = r + 9 * i;
            if (t == 0) {
                val = 0.f;
            } else {
                val = s[t] - s[t - 1];
            }
            if (t == 5) val += s[0];
        }
        v[k] = val;
    }
    __syncthreads();   // shared now free to be overwritten with results

    // 3) warp scan with sequential carry across tiles
    float carry = 0.f;
    #pragma unroll
    for (int k = 0; k < NTILES; k++) {
        float val = v[k];
        #pragma unroll
        for (int off = 1; off < 32; off <<= 1) {
            float up = __shfl_up_sync(0xffffffffu, val, off);
            if (lane >= off) val += up;
        }
        val += carry;
        carry = __shfl_sync(0xffffffffu, val, 31);
        const int i = 32 * k + lane;
        if (i < n) s[r + 9 * i] = 8.f * val;
    }
    __syncthreads();

    // 4) coalesced store
    #pragma unroll
    for (int i = threadIdx.x; i < ROW_T / 4; i += NTHREADS) {
        outr[i] = ((const float4*)s)[i];
    }
}

extern "C" void kernel_launch(void* const* d_in, const int* in_sizes, int n_in,
                              void* d_out, int out_size) {
    const float* x = (const float*)d_in[0];
    float* out = (float*)d_out;
    const int rows = in_sizes[0] / ROW_T;   // 64*256 = 16384
    inv_avgpool_kernel<<<rows, NTHREADS>>>(x, out);
}

// round 2
// speedup vs baseline: 1.1368x; 1.1368x over previous
#include <cuda_runtime.h>
#include <cuda_bf16.h>

// InverseAvgPool1d, K=8 -> half=4, s=9.
// out[t] = 8*(A[t] - A[t-1]) + 8*x0*( [t%9==5] - [t%9==0] ),
// where A[t] = sum_{i>=0, t-9i>=0} x[t-9i]  (stride-9 prefix of x), A[-1]=0.

#define ROW_T 4096
#define NWARP 9
#define NTHREADS (NWARP * 32)   // 288
#define PER_LANE 15             // 32*15 = 480 >= 456 (longest chain)

__global__ __launch_bounds__(NTHREADS)
void inv_avgpool_kernel(const float* __restrict__ x, float* __restrict__ out) {
    __shared__ float s[ROW_T];

    const size_t row = blockIdx.x;
    const float4* __restrict__ xr = (const float4*)(x + row * ROW_T);
    float4* __restrict__ outr = (float4*)(out + row * ROW_T);

    // 1) coalesced stage: 1024 float4
    #pragma unroll
    for (int i = threadIdx.x; i < ROW_T / 4; i += NTHREADS) {
        ((float4*)s)[i] = xr[i];
    }
    __syncthreads();

    const int lane = threadIdx.x & 31;
    const int r = threadIdx.x >> 5;          // warp id = residue chain r (0..8)
    const float x0 = s[0];                   // needed later, s gets overwritten

    // 2) lane l serially accumulates chain indices [15l, 15l+15)
    //    (1 conflict-free LDS per element; adds on the idle FMA/ALU pipe)
    const int n = (r == 0) ? 456 : 455;      // chain length
    const int i0 = PER_LANE * lane;

    float a[PER_LANE];
    float run = 0.f;
    #pragma unroll
    for (int j = 0; j < PER_LANE; j++) {
        const int i = i0 + j;
        if (i < n) run += s[r + 9 * i];
        a[j] = run;
    }
    __syncthreads();   // all x reads complete; s free for A writeback

    // 3) one warp scan over lane totals (5 shfls), exclusive carry per lane
    float incl = run;
    #pragma unroll
    for (int off = 1; off < 32; off <<= 1) {
        float up = __shfl_up_sync(0xffffffffu, incl, off);
        if (lane >= off) incl += up;
    }
    const float excl = incl - run;

    // 4) write 8*A back to shared (conflict-free strided STS.32)
    #pragma unroll
    for (int j = 0; j < PER_LANE; j++) {
        const int i = i0 + j;
        if (i < n) s[r + 9 * i] = 8.f * (excl + a[j]);
    }
    __syncthreads();

    // 5) coalesced diff pass: out[t] = s8A[t] - s8A[t-1] + 8*x0*corr(t%9)
    const float c8 = 8.f * x0;
    #pragma unroll
    for (int q = threadIdx.x; q < ROW_T / 4; q += NTHREADS) {
        float4 B = ((const float4*)s)[q];

        // previous element: in-register for .y/.z/.w, shfl (+smem for lane 0) for .x
        float prevw = __shfl_up_sync(0xffffffffu, B.w, 1);
        if (lane == 0) prevw = (q == 0) ? 0.f : s[4 * q - 1];

        const int t0 = 4 * q;
        int rr = t0 % 9;

        float4 o;
        o.x = B.x - prevw;
        if (rr == 5) o.x += c8; else if (rr == 0) o.x -= c8;
        rr = (rr == 8) ? 0 : rr + 1;
        o.y = B.y - B.x;
        if (rr == 5) o.y += c8; else if (rr == 0) o.y -= c8;
        rr = (rr == 8) ? 0 : rr + 1;
        o.z = B.z - B.y;
        if (rr == 5) o.z += c8; else if (rr == 0) o.z -= c8;
        rr = (rr == 8) ? 0 : rr + 1;
        o.w = B.w - B.z;
        if (rr == 5) o.w += c8; else if (rr == 0) o.w -= c8;

        outr[q] = o;
    }
}

extern "C" void kernel_launch(void* const* d_in, const int* in_sizes, int n_in,
                              void* d_out, int out_size) {
    const float* x = (const float*)d_in[0];
    float* out = (float*)d_out;
    const int rows = in_sizes[0] / ROW_T;   // 64*256 = 16384
    inv_avgpool_kernel<<<rows, NTHREADS>>>(x, out);
}

// round 3
// speedup vs baseline: 1.4301x; 1.2580x over previous
#include <cuda_runtime.h>
#include <cuda_bf16.h>

// InverseAvgPool1d, K=8 -> half=4, s=9.
// out[t] = 8*(A[t] - A[t-1]) + 8*x0*( [t%9==5] - [t%9==0] ),
// where A[t] = stride-9 prefix sum of x along the row, A[-1]=0.

#define ROW_T 4096
#define PAD_T 4320              // >= 8 + 9*479 + 1; tail zero-filled
#define NWARP 9
#define NTHREADS (NWARP * 32)   // 288
#define PER_LANE 15             // 32*15 = 480 slots per chain (456 real max)

__global__ __launch_bounds__(NTHREADS)
void inv_avgpool_kernel(const float* __restrict__ x, float* __restrict__ out) {
    __shared__ float s[PAD_T];

    const size_t row = blockIdx.x;
    const float4* __restrict__ xr = (const float4*)(x + row * ROW_T);
    float4* __restrict__ outr = (float4*)(out + row * ROW_T);

    // 1) coalesced stage (1024 float4) + zero-fill pad tail
    #pragma unroll
    for (int i = threadIdx.x; i < ROW_T / 4; i += NTHREADS) {
        ((float4*)s)[i] = xr[i];
    }
    if (threadIdx.x < PAD_T - ROW_T) s[ROW_T + threadIdx.x] = 0.f;
    __syncthreads();

    const int lane = threadIdx.x & 31;
    const int r = threadIdx.x >> 5;          // warp id = residue chain (0..8)
    const float x0 = s[0];

    // 2) lane l serially accumulates chain slots [15l, 15l+15) — unpredicated,
    //    base computed once, offsets are immediates. Conflict-free (stride 9).
    const int base = r + 135 * lane;         // r + 9*(15*lane)
    float a[PER_LANE];
    float run = 0.f;
    #pragma unroll
    for (int j = 0; j < PER_LANE; j++) {
        run += s[base + 9 * j];
        a[j] = run;
    }
    __syncthreads();                         // s free for A writeback

    // 3) warp scan over lane totals (5 shfls) -> exclusive carry
    float incl = run;
    #pragma unroll
    for (int off = 1; off < 32; off <<= 1) {
        float up = __shfl_up_sync(0xffffffffu, incl, off);
        if (lane >= off) incl += up;
    }
    const float e8 = 8.f * (incl - run);     // 8 * exclusive carry

    // 4) write 8*A back (unpredicated; overflow lands in pad) — FFMA each
    #pragma unroll
    for (int j = 0; j < PER_LANE; j++) {
        s[base + 9 * j] = fmaf(8.f, a[j], e8);
    }
    __syncthreads();

    // 5) coalesced diff pass. t0 = 4*(tid + 288k); 1152 % 9 == 0, so the
    //    residue pattern is loop-invariant per thread: hoist corrections.
    const float c8 = 8.f * x0;
    const int rr0 = (4 * threadIdx.x) % 9;
    const int rr1 = (rr0 + 1) % 9, rr2 = (rr0 + 2) % 9, rr3 = (rr0 + 3) % 9;
    const float addx = (rr0 == 5) ? c8 : (rr0 == 0) ? -c8 : 0.f;
    const float addy = (rr1 == 5) ? c8 : (rr1 == 0) ? -c8 : 0.f;
    const float addz = (rr2 == 5) ? c8 : (rr2 == 0) ? -c8 : 0.f;
    const float addw = (rr3 == 5) ? c8 : (rr3 == 0) ? -c8 : 0.f;

    #pragma unroll
    for (int q = threadIdx.x; q < ROW_T / 4; q += NTHREADS) {
        float4 B = ((const float4*)s)[q];

        float prevw = __shfl_up_sync(0xffffffffu, B.w, 1);
        if (lane == 0) prevw = (q == 0) ? 0.f : s[4 * q - 1];

        float4 o;
        o.x = (B.x - prevw) + addx;
        o.y = (B.y - B.x) + addy;
        o.z = (B.z - B.y) + addz;
        o.w = (B.w - B.z) + addw;
        outr[q] = o;
    }
}

extern "C" void kernel_launch(void* const* d_in, const int* in_sizes, int n_in,
                              void* d_out, int out_size) {
    const float* x = (const float*)d_in[0];
    float* out = (float*)d_out;
    const int rows = in_sizes[0] / ROW_T;   // 64*256 = 16384
    inv_avgpool_kernel<<<rows, NTHREADS>>>(x, out);
}